// round 3
// baseline (speedup 1.0000x reference)
#include <cuda_runtime.h>
#include <cuda_bf16.h>
#include <cstdint>

#define BATCH   16
#define NPRED   25200
#define NC      80
#define STRIDE  85
#define TOPK    4096
#define MAXDET  1000
#define NWORDS  64            // TOPK/64
#define NITEMS  25            // ceil(NPRED/1024)
#define CONF_THRES 0.25f
#define IOU_THRES  0.45f
#define MAX_WH     7680.0f

typedef unsigned long long ull;

// ---------------- scratch (no allocation allowed; __device__ globals) ----------------
__device__ unsigned  g_u[BATCH * NPRED];        // order key (score part)
__device__ float     g_s[BATCH * NPRED];        // s = valid ? conf : -1
__device__ int       g_cls[BATCH * NPRED];      // argmax class
__device__ float     g_selScore[BATCH * TOPK];
__device__ int       g_selCls[BATCH * TOPK];
__device__ unsigned  g_clsPack[BATCH * TOPK / 4]; // classes as packed bytes
__device__ float     g_box[BATCH * TOPK * 4];   // xyxy (no offset)
__device__ float     g_ob[BATCH * TOPK * 4];    // offset boxes
__device__ float     g_area[BATCH * TOPK];      // area of offset box
__device__ ull       g_mask[(size_t)BATCH * TOPK * NWORDS]; // 32MB
__device__ ull       g_keep[BATCH * NWORDS];
__device__ int       g_nvalid[BATCH];

// ---------------- kernel 1: conf / argmax / order-key, one warp per row --------------
__global__ void k_prep(const float* __restrict__ pred) {
    int gw   = (blockIdx.x * blockDim.x + threadIdx.x) >> 5;  // global warp = row
    int lane = threadIdx.x & 31;
    if (gw >= BATCH * NPRED) return;
    const float* p = pred + (size_t)gw * STRIDE;
    float obj = p[4];
    float best = -1.0f; int bi = 0;
    #pragma unroll
    for (int c = lane; c < NC; c += 32) {
        float v = __fmul_rn(obj, p[5 + c]);
        if (v > best) { best = v; bi = c; }          // strict > keeps first max
    }
    #pragma unroll
    for (int o = 16; o; o >>= 1) {
        float b2 = __shfl_xor_sync(0xFFFFFFFFu, best, o);
        int   i2 = __shfl_xor_sync(0xFFFFFFFFu, bi, o);
        if (b2 > best || (b2 == best && i2 < bi)) { best = b2; bi = i2; }
    }
    if (lane == 0) {
        float s = (best > CONF_THRES) ? best : -1.0f;
        unsigned ub = __float_as_uint(s);
        unsigned uo = (ub & 0x80000000u) ? ~ub : (ub | 0x80000000u); // ascending order map
        g_s[gw] = s; g_u[gw] = uo; g_cls[gw] = bi;
    }
}

// ---------------- kernel 2: top-4096 (reg keys + 2-bit search) + hybrid bitonic ------
__device__ __forceinline__ ull shfl_xor_u64(ull x, int m) {
    unsigned lo = __shfl_xor_sync(0xFFFFFFFFu, (unsigned)x, m);
    unsigned hi = __shfl_xor_sync(0xFFFFFFFFu, (unsigned)(x >> 32), m);
    return ((ull)hi << 32) | lo;
}

__global__ void __launch_bounds__(1024) k_select(const float* __restrict__ pred) {
    int b = blockIdx.x;
    int tid = threadIdx.x;
    int lane = tid & 31;
    const unsigned* u = g_u + b * NPRED;
    __shared__ ull keys[TOPK];
    __shared__ ull sT;
    __shared__ int sCnt0, sCnt1, sCnt2;
    __shared__ int scnt, svalid;

    // ---- load all keys into registers (full MLP, one pass over memory) ----
    unsigned uv[NITEMS];
    #pragma unroll
    for (int k = 0; k < NITEMS; ++k) {
        int i = k * 1024 + tid;
        uv[k] = (i < NPRED) ? u[i] : 0u;
    }
    if (tid == 0) { sT = 0ULL; sCnt0 = 0; sCnt1 = 0; sCnt2 = 0; scnt = 0; svalid = 0; }
    __syncthreads();

    // ---- 2-bit-per-step binary search for T = TOPK-th largest key ((u<<32)|~i) ----
    for (int s = 62; s >= 0; s -= 2) {
        ull T = sT;
        ull c1t = T + (1ULL << s);
        int c1 = 0, c2 = 0, c3 = 0;
        #pragma unroll
        for (int k = 0; k < NITEMS; ++k) {
            int i = k * 1024 + tid;
            if (i < NPRED) {
                ull key = ((ull)uv[k] << 32) | (unsigned)(~i);
                if (key >= c1t) {
                    ull w = (key - T) >> s;
                    c1++;
                    if (w >= 2) c2++;
                    if (w >= 3) c3++;
                }
            }
        }
        c1 = __reduce_add_sync(0xFFFFFFFFu, c1);
        c2 = __reduce_add_sync(0xFFFFFFFFu, c2);
        c3 = __reduce_add_sync(0xFFFFFFFFu, c3);
        if (lane == 0) {
            atomicAdd(&sCnt0, c1);
            atomicAdd(&sCnt1, c2);
            atomicAdd(&sCnt2, c3);
        }
        __syncthreads();
        if (tid == 0) {
            int v = (sCnt2 >= TOPK) ? 3 : (sCnt1 >= TOPK) ? 2 : (sCnt0 >= TOPK) ? 1 : 0;
            sT = T | ((ull)v << s);
            sCnt0 = 0; sCnt1 = 0; sCnt2 = 0;
        }
        __syncthreads();
    }
    ull T = sT;

    // ---- gather exactly-4096 keys >= T (warp-aggregated positions) ----
    #pragma unroll
    for (int k = 0; k < NITEMS; ++k) {
        int i = k * 1024 + tid;
        bool m = (i < NPRED);
        ull key = 0ULL;
        if (m) { key = ((ull)uv[k] << 32) | (unsigned)(~i); m = (key >= T); }
        unsigned act = __ballot_sync(0xFFFFFFFFu, m);
        if (m) {
            int leader = __ffs(act) - 1;
            int rank = __popc(act & ((1u << lane) - 1u));
            int base;
            if (lane == leader) base = atomicAdd(&scnt, __popc(act));
            base = __shfl_sync(act, base, leader);
            int pos = base + rank;
            if (pos < TOPK) keys[pos] = key;
        }
    }
    __syncthreads();

    // ---- hybrid bitonic sort, descending: 4 elems/thread (blocked) ----
    ull v[4];
    #pragma unroll
    for (int e = 0; e < 4; ++e) v[e] = keys[tid * 4 + e];

    for (int k = 2; k <= TOPK; k <<= 1) {
        for (int j = k >> 1; j >= 1; j >>= 1) {
            if (j >= 128) {
                // shared exchange
                #pragma unroll
                for (int e = 0; e < 4; ++e) keys[tid * 4 + e] = v[e];
                __syncthreads();
                #pragma unroll
                for (int e = 0; e < 4; ++e) {
                    int idx = tid * 4 + e;
                    ull pv = keys[idx ^ j];
                    bool d = ((idx & k) == 0);
                    bool lower = ((idx & j) == 0);
                    bool keepmax = (d == lower);
                    ull mx = (v[e] > pv) ? v[e] : pv;
                    ull mn = (v[e] > pv) ? pv : v[e];
                    v[e] = keepmax ? mx : mn;
                }
                __syncthreads();
            } else if (j >= 4) {
                // intra-warp shuffle exchange (partner thread = tid ^ (j/4))
                int dl = j >> 2;
                #pragma unroll
                for (int e = 0; e < 4; ++e) {
                    ull pv = shfl_xor_u64(v[e], dl);
                    int idx = tid * 4 + e;
                    bool d = ((idx & k) == 0);
                    bool lower = ((tid & dl) == 0);
                    bool keepmax = (d == lower);
                    ull mx = (v[e] > pv) ? v[e] : pv;
                    ull mn = (v[e] > pv) ? pv : v[e];
                    v[e] = keepmax ? mx : mn;
                }
            } else {
                // intra-thread (j == 1 or 2)
                #pragma unroll
                for (int e = 0; e < 4; ++e) {
                    if ((e & j) == 0) {
                        int idx = tid * 4 + e;
                        bool d = ((idx & k) == 0);
                        ull a = v[e], c2 = v[e + j];
                        if (d ? (a < c2) : (a > c2)) { v[e] = c2; v[e + j] = a; }
                    }
                }
            }
        }
    }

    // ---- emit + fused gather of boxes / classes / areas ----
    int lv = 0;
    #pragma unroll
    for (int e = 0; e < 4; ++e) {
        int rank = tid * 4 + e;
        ull key = v[e];
        int i = (int)(~(unsigned)(key & 0xFFFFFFFFull));
        int gi = b * TOPK + rank;
        float s = g_s[b * NPRED + i];
        g_selScore[gi] = s;
        lv += (s > 0.0f);
        int ci = g_cls[b * NPRED + i];
        g_selCls[gi] = ci;
        ((unsigned char*)g_clsPack)[gi] = (unsigned char)ci;
        const float* p = pred + ((size_t)b * NPRED + i) * STRIDE;
        float xc = p[0], yc = p[1], w = p[2], h = p[3];
        float hw = __fmul_rn(w, 0.5f), hh = __fmul_rn(h, 0.5f);
        float x1 = __fsub_rn(xc, hw), y1 = __fsub_rn(yc, hh);
        float x2 = __fadd_rn(xc, hw), y2 = __fadd_rn(yc, hh);
        float off = __fmul_rn((float)ci, MAX_WH);
        float ox1 = __fadd_rn(x1, off), oy1 = __fadd_rn(y1, off);
        float ox2 = __fadd_rn(x2, off), oy2 = __fadd_rn(y2, off);
        ((float4*)g_box)[gi] = make_float4(x1, y1, x2, y2);
        ((float4*)g_ob)[gi]  = make_float4(ox1, oy1, ox2, oy2);
        g_area[gi] = __fmul_rn(__fsub_rn(ox2, ox1), __fsub_rn(oy2, oy1));
    }
    lv = __reduce_add_sync(0xFFFFFFFFu, lv);
    if (lane == 0) atomicAdd(&svalid, lv);
    __syncthreads();
    if (tid == 0) g_nvalid[b] = svalid;
}

// ---------------- kernel 3: pairwise suppression mask (upper triangle) ---------------
__global__ void __launch_bounds__(256) k_mask() {
    int colBlk = blockIdx.x;            // 0..63
    int rowQuad = blockIdx.y;           // 0..15 (4 row tiles each)
    int b = blockIdx.z;
    if (colBlk < rowQuad * 4) return;   // entire block below diagonal
    int t = threadIdx.x;
    int sub = t >> 6, l = t & 63;
    __shared__ float4 cb[64];
    __shared__ float  ca[64];
    __shared__ unsigned ccp[16];
    int colBase = colBlk * 64;
    if (t < 64) {
        int gj = b * TOPK + colBase + t;
        cb[t] = ((const float4*)g_ob)[gj];
        ca[t] = g_area[gj];
    } else if (t < 80) {
        ccp[t - 64] = g_clsPack[b * (TOPK / 4) + colBlk * 16 + (t - 64)];
    }
    __syncthreads();
    int rowBlk = rowQuad * 4 + sub;
    if (colBlk < rowBlk) return;        // sub-tile below diagonal (no more syncs below)
    int i = rowBlk * 64 + l;
    int gi = b * TOPK + i;
    float4 rb = ((const float4*)g_ob)[gi];
    float ra = g_area[gi];
    unsigned rc = ((const unsigned char*)g_clsPack)[gi];
    unsigned rc4 = rc * 0x01010101u;
    // branchless same-class candidate mask via packed byte compares
    unsigned lo = 0, hi = 0;
    #pragma unroll
    for (int w = 0; w < 8; ++w) {
        unsigned m = __vcmpeq4(ccp[w], rc4) & 0x01010101u;
        lo |= ((m * 0x01020408u) >> 24) << (4 * w);
    }
    #pragma unroll
    for (int w = 8; w < 16; ++w) {
        unsigned m = __vcmpeq4(ccp[w], rc4) & 0x01010101u;
        hi |= ((m * 0x01020408u) >> 24) << (4 * (w - 8));
    }
    ull cand = ((ull)hi << 32) | (ull)lo;
    if (colBlk == rowBlk) cand = (l == 63) ? 0ULL : (cand & (~0ULL << (l + 1)));
    ull bits = 0ULL;
    while (cand) {
        int c = __ffsll((long long)cand) - 1;
        cand &= cand - 1;
        float4 cc = cb[c];
        float ltx = fmaxf(rb.x, cc.x);
        float lty = fmaxf(rb.y, cc.y);
        float rbx = fminf(rb.z, cc.z);
        float rby = fminf(rb.w, cc.w);
        float wv = fmaxf(__fsub_rn(rbx, ltx), 0.0f);
        float hv = fmaxf(__fsub_rn(rby, lty), 0.0f);
        float inter = __fmul_rn(wv, hv);
        if (inter > 0.0f) {
            float denom = __fadd_rn(__fsub_rn(__fadd_rn(ra, ca[c]), inter), 1e-7f);
            if (__fdiv_rn(inter, denom) > IOU_THRES) bits |= (1ULL << c);
        }
    }
    g_mask[((size_t)b * TOPK + i) * NWORDS + colBlk] = bits;
}

// ---------------- kernel 4: sequential greedy suppression (blocked, prefetched) ------
__global__ void __launch_bounds__(256) k_suppress() {
    int b = blockIdx.x;
    int tid = threadIdx.x;   // 256
    __shared__ ull removed[NWORDS];
    __shared__ ull diag[64];
    __shared__ ull sAlive;
    int nv = g_nvalid[b];
    size_t mb = (size_t)b * TOPK * NWORDS;
    if (tid < NWORDS) removed[tid] = 0ULL;
    ull dreg = 0ULL;
    if (tid < 64) dreg = g_mask[mb + (size_t)tid * NWORDS];   // diag block 0
    for (int blk = 0; blk < NWORDS; ++blk) {
        if (tid < 64) diag[tid] = dreg;
        __syncthreads();
        // prefetch next diagonal block while the serial phase runs
        if (blk + 1 < NWORDS && tid < 64)
            dreg = g_mask[mb + (size_t)((blk + 1) * 64 + tid) * NWORDS + (blk + 1)];
        if (tid == 0) {
            ull w = removed[blk], alive = 0ULL;
            int lim = nv - blk * 64; if (lim > 64) lim = 64;
            #pragma unroll 8
            for (int bb = 0; bb < 64; ++bb) {
                if (bb < lim && !((w >> bb) & 1ULL)) {
                    alive |= (1ULL << bb);
                    w |= diag[bb];
                }
            }
            removed[blk] = w;
            sAlive = alive;
            g_keep[b * NWORDS + blk] = alive;
        }
        __syncthreads();
        ull alive = sAlive;
        if (alive) {
            int lane = tid & 63, grp = tid >> 6;
            int w = blk + 1 + lane;
            if (w < NWORDS) {
                ull acc = 0ULL;
                #pragma unroll 4
                for (int bb = grp; bb < 64; bb += 4) {
                    if ((alive >> bb) & 1ULL)
                        acc |= g_mask[mb + (size_t)(blk * 64 + bb) * NWORDS + w];
                }
                if (acc) atomicOr(&removed[w], acc);
            }
        }
    }
}

// ---------------- kernel 5: compact kept detections into output ----------------------
__global__ void k_output(float* __restrict__ out) {
    int b = blockIdx.x;
    int tid = threadIdx.x;   // 256
    __shared__ ull km[NWORDS];
    __shared__ int prefix[NWORDS + 1];
    if (tid < NWORDS) km[tid] = g_keep[b * NWORDS + tid];
    __syncthreads();
    if (tid == 0) {
        int s = 0;
        for (int w = 0; w < NWORDS; ++w) { prefix[w] = s; s += __popcll(km[w]); }
        prefix[NWORDS] = s;
    }
    float* o = out + (size_t)b * MAXDET * 6;
    for (int z = tid; z < MAXDET * 6; z += 256) o[z] = 0.0f;
    __syncthreads();
    for (int i = tid; i < TOPK; i += 256) {
        int w = i >> 6, bt = i & 63;
        if ((km[w] >> bt) & 1ULL) {
            int rank = prefix[w] + __popcll(km[w] & ((1ULL << bt) - 1ULL));
            if (rank < MAXDET) {
                int gi = b * TOPK + i;
                float* r = o + rank * 6;
                float4 bx = ((const float4*)g_box)[gi];
                r[0] = bx.x; r[1] = bx.y; r[2] = bx.z; r[3] = bx.w;
                r[4] = g_selScore[gi];
                r[5] = (float)g_selCls[gi];
            }
        }
    }
}

// ---------------- launch ---------------------------------------------------------------
extern "C" void kernel_launch(void* const* d_in, const int* in_sizes, int n_in,
                              void* d_out, int out_size) {
    const float* pred = (const float*)d_in[0];
    float* out = (float*)d_out;

    // 1) conf / argmax / order key : one warp per row
    {
        int rows = BATCH * NPRED;
        int threads = 256;
        int blocks = (rows * 32 + threads - 1) / threads;
        k_prep<<<blocks, threads>>>(pred);
    }
    // 2) exact top-4096 per batch + sort + fused gather
    k_select<<<BATCH, 1024>>>(pred);
    // 3) pairwise IoU mask (4 row-tiles per block)
    {
        dim3 g(NWORDS, NWORDS / 4, BATCH);
        k_mask<<<g, 256>>>();
    }
    // 4) greedy suppression
    k_suppress<<<BATCH, 256>>>();
    // 5) compact output
    k_output<<<BATCH, 256>>>(out);
}

// round 4
// speedup vs baseline: 1.2082x; 1.2082x over previous
#include <cuda_runtime.h>
#include <cuda_bf16.h>
#include <cstdint>

#define BATCH   16
#define NPRED   25200
#define NC      80
#define STRIDE  85
#define TOPK    4096
#define MAXDET  1000
#define NWORDS  64            // TOPK/64
#define NITEMS  25            // ceil(NPRED/1024)
#define CONF_THRES 0.25f
#define IOU_THRES  0.45f
#define MAX_WH     7680.0f

typedef unsigned long long ull;

// ---------------- scratch (no allocation allowed; __device__ globals) ----------------
__device__ unsigned  g_u[BATCH * NPRED];        // order key (score part)
__device__ float     g_s[BATCH * NPRED];        // s = valid ? conf : -1
__device__ int       g_cls[BATCH * NPRED];      // argmax class
__device__ float     g_selScore[BATCH * TOPK];
__device__ int       g_selCls[BATCH * TOPK];
__device__ unsigned  g_clsPack[BATCH * TOPK / 4]; // classes as packed bytes
__device__ float     g_box[BATCH * TOPK * 4];   // xyxy (no offset)
__device__ float     g_ob[BATCH * TOPK * 4];    // offset boxes
__device__ float     g_area[BATCH * TOPK];      // area of offset box
__device__ ull       g_mask[(size_t)BATCH * TOPK * NWORDS]; // 32MB
__device__ int       g_nvalid[BATCH];

// ---------------- kernel 1: conf / argmax / order-key, one warp per row --------------
__global__ void k_prep(const float* __restrict__ pred) {
    int gw   = (blockIdx.x * blockDim.x + threadIdx.x) >> 5;  // global warp = row
    int lane = threadIdx.x & 31;
    if (gw >= BATCH * NPRED) return;
    const float* p = pred + (size_t)gw * STRIDE;
    float obj = p[4];
    float best = -1.0f; int bi = 0;
    #pragma unroll
    for (int c = lane; c < NC; c += 32) {
        float v = __fmul_rn(obj, p[5 + c]);
        if (v > best) { best = v; bi = c; }          // strict > keeps first max
    }
    #pragma unroll
    for (int o = 16; o; o >>= 1) {
        float b2 = __shfl_xor_sync(0xFFFFFFFFu, best, o);
        int   i2 = __shfl_xor_sync(0xFFFFFFFFu, bi, o);
        if (b2 > best || (b2 == best && i2 < bi)) { best = b2; bi = i2; }
    }
    if (lane == 0) {
        float s = (best > CONF_THRES) ? best : -1.0f;
        unsigned ub = __float_as_uint(s);
        unsigned uo = (ub & 0x80000000u) ? ~ub : (ub | 0x80000000u); // ascending order map
        g_s[gw] = s; g_u[gw] = uo; g_cls[gw] = bi;
    }
}

// ---------------- kernel 2: top-4096 (reg keys + 2-bit search) + hybrid bitonic ------
__device__ __forceinline__ ull shfl_xor_u64(ull x, int m) {
    unsigned lo = __shfl_xor_sync(0xFFFFFFFFu, (unsigned)x, m);
    unsigned hi = __shfl_xor_sync(0xFFFFFFFFu, (unsigned)(x >> 32), m);
    return ((ull)hi << 32) | lo;
}

__global__ void __launch_bounds__(1024) k_select(const float* __restrict__ pred) {
    int b = blockIdx.x;
    int tid = threadIdx.x;
    int lane = tid & 31;
    const unsigned* u = g_u + b * NPRED;
    __shared__ ull keys[TOPK];
    __shared__ ull sT;
    __shared__ int sCnt0, sCnt1, sCnt2;
    __shared__ int scnt, svalid;

    // ---- load all keys into registers (full MLP, one pass over memory) ----
    unsigned uv[NITEMS];
    #pragma unroll
    for (int k = 0; k < NITEMS; ++k) {
        int i = k * 1024 + tid;
        uv[k] = (i < NPRED) ? u[i] : 0u;
    }
    if (tid == 0) { sT = 0ULL; sCnt0 = 0; sCnt1 = 0; sCnt2 = 0; scnt = 0; svalid = 0; }
    __syncthreads();

    // ---- 2-bit-per-step binary search for T = TOPK-th largest key ((u<<32)|~i) ----
    for (int s = 62; s >= 0; s -= 2) {
        ull T = sT;
        ull c1t = T + (1ULL << s);
        int c1 = 0, c2 = 0, c3 = 0;
        #pragma unroll
        for (int k = 0; k < NITEMS; ++k) {
            int i = k * 1024 + tid;
            if (i < NPRED) {
                ull key = ((ull)uv[k] << 32) | (unsigned)(~i);
                if (key >= c1t) {
                    ull w = (key - T) >> s;
                    c1++;
                    if (w >= 2) c2++;
                    if (w >= 3) c3++;
                }
            }
        }
        c1 = __reduce_add_sync(0xFFFFFFFFu, c1);
        c2 = __reduce_add_sync(0xFFFFFFFFu, c2);
        c3 = __reduce_add_sync(0xFFFFFFFFu, c3);
        if (lane == 0) {
            atomicAdd(&sCnt0, c1);
            atomicAdd(&sCnt1, c2);
            atomicAdd(&sCnt2, c3);
        }
        __syncthreads();
        if (tid == 0) {
            int v = (sCnt2 >= TOPK) ? 3 : (sCnt1 >= TOPK) ? 2 : (sCnt0 >= TOPK) ? 1 : 0;
            sT = T | ((ull)v << s);
            sCnt0 = 0; sCnt1 = 0; sCnt2 = 0;
        }
        __syncthreads();
    }
    ull T = sT;

    // ---- gather exactly-4096 keys >= T (warp-aggregated positions) ----
    #pragma unroll
    for (int k = 0; k < NITEMS; ++k) {
        int i = k * 1024 + tid;
        bool m = (i < NPRED);
        ull key = 0ULL;
        if (m) { key = ((ull)uv[k] << 32) | (unsigned)(~i); m = (key >= T); }
        unsigned act = __ballot_sync(0xFFFFFFFFu, m);
        if (m) {
            int leader = __ffs(act) - 1;
            int rank = __popc(act & ((1u << lane) - 1u));
            int base;
            if (lane == leader) base = atomicAdd(&scnt, __popc(act));
            base = __shfl_sync(act, base, leader);
            int pos = base + rank;
            if (pos < TOPK) keys[pos] = key;
        }
    }
    __syncthreads();

    // ---- hybrid bitonic sort, descending: 4 elems/thread (blocked) ----
    ull v[4];
    #pragma unroll
    for (int e = 0; e < 4; ++e) v[e] = keys[tid * 4 + e];

    for (int k = 2; k <= TOPK; k <<= 1) {
        for (int j = k >> 1; j >= 1; j >>= 1) {
            if (j >= 128) {
                // shared exchange
                #pragma unroll
                for (int e = 0; e < 4; ++e) keys[tid * 4 + e] = v[e];
                __syncthreads();
                #pragma unroll
                for (int e = 0; e < 4; ++e) {
                    int idx = tid * 4 + e;
                    ull pv = keys[idx ^ j];
                    bool d = ((idx & k) == 0);
                    bool lower = ((idx & j) == 0);
                    bool keepmax = (d == lower);
                    ull mx = (v[e] > pv) ? v[e] : pv;
                    ull mn = (v[e] > pv) ? pv : v[e];
                    v[e] = keepmax ? mx : mn;
                }
                __syncthreads();
            } else if (j >= 4) {
                // intra-warp shuffle exchange (partner thread = tid ^ (j/4))
                int dl = j >> 2;
                #pragma unroll
                for (int e = 0; e < 4; ++e) {
                    ull pv = shfl_xor_u64(v[e], dl);
                    int idx = tid * 4 + e;
                    bool d = ((idx & k) == 0);
                    bool lower = ((tid & dl) == 0);
                    bool keepmax = (d == lower);
                    ull mx = (v[e] > pv) ? v[e] : pv;
                    ull mn = (v[e] > pv) ? pv : v[e];
                    v[e] = keepmax ? mx : mn;
                }
            } else {
                // intra-thread (j == 1 or 2)
                #pragma unroll
                for (int e = 0; e < 4; ++e) {
                    if ((e & j) == 0) {
                        int idx = tid * 4 + e;
                        bool d = ((idx & k) == 0);
                        ull a = v[e], c2 = v[e + j];
                        if (d ? (a < c2) : (a > c2)) { v[e] = c2; v[e + j] = a; }
                    }
                }
            }
        }
    }

    // ---- emit + fused gather of boxes / classes / areas ----
    int lv = 0;
    #pragma unroll
    for (int e = 0; e < 4; ++e) {
        int rank = tid * 4 + e;
        ull key = v[e];
        int i = (int)(~(unsigned)(key & 0xFFFFFFFFull));
        int gi = b * TOPK + rank;
        float s = g_s[b * NPRED + i];
        g_selScore[gi] = s;
        lv += (s > 0.0f);
        int ci = g_cls[b * NPRED + i];
        g_selCls[gi] = ci;
        ((unsigned char*)g_clsPack)[gi] = (unsigned char)ci;
        const float* p = pred + ((size_t)b * NPRED + i) * STRIDE;
        float xc = p[0], yc = p[1], w = p[2], h = p[3];
        float hw = __fmul_rn(w, 0.5f), hh = __fmul_rn(h, 0.5f);
        float x1 = __fsub_rn(xc, hw), y1 = __fsub_rn(yc, hh);
        float x2 = __fadd_rn(xc, hw), y2 = __fadd_rn(yc, hh);
        float off = __fmul_rn((float)ci, MAX_WH);
        float ox1 = __fadd_rn(x1, off), oy1 = __fadd_rn(y1, off);
        float ox2 = __fadd_rn(x2, off), oy2 = __fadd_rn(y2, off);
        ((float4*)g_box)[gi] = make_float4(x1, y1, x2, y2);
        ((float4*)g_ob)[gi]  = make_float4(ox1, oy1, ox2, oy2);
        g_area[gi] = __fmul_rn(__fsub_rn(ox2, ox1), __fsub_rn(oy2, oy1));
    }
    lv = __reduce_add_sync(0xFFFFFFFFu, lv);
    if (lane == 0) atomicAdd(&svalid, lv);
    __syncthreads();
    if (tid == 0) g_nvalid[b] = svalid;
}

// ---------------- kernel 3: pairwise suppression mask (upper triangle) ---------------
__global__ void __launch_bounds__(256) k_mask() {
    int colBlk = blockIdx.x;            // 0..63
    int rowQuad = blockIdx.y;           // 0..15 (4 row tiles each)
    int b = blockIdx.z;
    if (colBlk < rowQuad * 4) return;   // entire block below diagonal
    int t = threadIdx.x;
    int sub = t >> 6, l = t & 63;
    __shared__ float4 cb[64];
    __shared__ float  ca[64];
    __shared__ unsigned ccp[16];
    int colBase = colBlk * 64;
    if (t < 64) {
        int gj = b * TOPK + colBase + t;
        cb[t] = ((const float4*)g_ob)[gj];
        ca[t] = g_area[gj];
    } else if (t < 80) {
        ccp[t - 64] = g_clsPack[b * (TOPK / 4) + colBlk * 16 + (t - 64)];
    }
    __syncthreads();
    int rowBlk = rowQuad * 4 + sub;
    if (colBlk < rowBlk) return;        // sub-tile below diagonal (no more syncs below)
    int i = rowBlk * 64 + l;
    int gi = b * TOPK + i;
    float4 rb = ((const float4*)g_ob)[gi];
    float ra = g_area[gi];
    unsigned rc = ((const unsigned char*)g_clsPack)[gi];
    unsigned rc4 = rc * 0x01010101u;
    // branchless same-class candidate mask via packed byte compares
    unsigned lo = 0, hi = 0;
    #pragma unroll
    for (int w = 0; w < 8; ++w) {
        unsigned m = __vcmpeq4(ccp[w], rc4) & 0x01010101u;
        lo |= ((m * 0x01020408u) >> 24) << (4 * w);
    }
    #pragma unroll
    for (int w = 8; w < 16; ++w) {
        unsigned m = __vcmpeq4(ccp[w], rc4) & 0x01010101u;
        hi |= ((m * 0x01020408u) >> 24) << (4 * (w - 8));
    }
    ull cand = ((ull)hi << 32) | (ull)lo;
    if (colBlk == rowBlk) cand = (l == 63) ? 0ULL : (cand & (~0ULL << (l + 1)));
    ull bits = 0ULL;
    while (cand) {
        int c = __ffsll((long long)cand) - 1;
        cand &= cand - 1;
        float4 cc = cb[c];
        float ltx = fmaxf(rb.x, cc.x);
        float lty = fmaxf(rb.y, cc.y);
        float rbx = fminf(rb.z, cc.z);
        float rby = fminf(rb.w, cc.w);
        float wv = fmaxf(__fsub_rn(rbx, ltx), 0.0f);
        float hv = fmaxf(__fsub_rn(rby, lty), 0.0f);
        float inter = __fmul_rn(wv, hv);
        if (inter > 0.0f) {
            float denom = __fadd_rn(__fsub_rn(__fadd_rn(ra, ca[c]), inter), 1e-7f);
            if (__fdiv_rn(inter, denom) > IOU_THRES) bits |= (1ULL << c);
        }
    }
    g_mask[((size_t)b * TOPK + i) * NWORDS + colBlk] = bits;
}

// ------- kernel 4: greedy suppression (register-prefetched, pipelined) + output ------
__global__ void __launch_bounds__(1024) k_suppress(float* __restrict__ out) {
    int b = blockIdx.x;
    int tid = threadIdx.x;   // 1024
    __shared__ ull removed[NWORDS];
    __shared__ ull keepw[NWORDS];
    __shared__ ull sAlive;
    __shared__ ull diag[64];
    __shared__ int prefix[NWORDS];
    int nv = g_nvalid[b];
    size_t mb = (size_t)b * TOPK * NWORDS;
    if (tid < NWORDS) removed[tid] = 0ULL;
    int lane = tid & 63;   // word offset
    int grp  = tid >> 6;   // 16 groups; rows bb = grp + e*16

    // prefetch diag word tile for blk 0 and row tile for blk 0 (unconditional loads)
    ull dreg = (tid < 64) ? g_mask[mb + (size_t)tid * NWORDS] : 0ULL;
    ull pre[4];
    {
        int w = 1 + lane;
        #pragma unroll
        for (int e = 0; e < 4; ++e) {
            int bb = grp + e * 16;
            pre[e] = (w < NWORDS) ? g_mask[mb + (size_t)bb * NWORDS + w] : 0ULL;
        }
    }

    for (int blk = 0; blk < NWORDS; ++blk) {
        if (tid < 64) diag[tid] = dreg;
        __syncthreads();
        // prefetch next diagonal tile during serial phase
        if (blk + 1 < NWORDS && tid < 64)
            dreg = g_mask[mb + (size_t)((blk + 1) * 64 + tid) * NWORDS + (blk + 1)];
        if (tid == 0) {
            ull w = removed[blk], alive = 0ULL;
            int lim = nv - blk * 64; if (lim > 64) lim = 64;
            #pragma unroll 8
            for (int bb = 0; bb < 64; ++bb) {
                if (bb < lim && !((w >> bb) & 1ULL)) {
                    alive |= (1ULL << bb);
                    w |= diag[bb];
                }
            }
            removed[blk] = w;
            sAlive = alive;
            keepw[blk] = alive;
        }
        __syncthreads();
        ull alive = sAlive;
        // apply alive filter to the prefetched row tile (registers, no memory wait)
        {
            int w = blk + 1 + lane;
            if (w < NWORDS) {
                ull acc = 0ULL;
                #pragma unroll
                for (int e = 0; e < 4; ++e) {
                    int bb = grp + e * 16;
                    if ((alive >> bb) & 1ULL) acc |= pre[e];
                }
                if (acc) atomicOr(&removed[w], acc);
            }
        }
        // prefetch row tile for blk+1 (flies during next serial phase)
        if (blk + 1 < NWORDS) {
            int w2 = blk + 2 + lane;
            #pragma unroll
            for (int e = 0; e < 4; ++e) {
                int bb = grp + e * 16;
                pre[e] = (w2 < NWORDS) ? g_mask[mb + (size_t)((blk + 1) * 64 + bb) * NWORDS + w2] : 0ULL;
            }
        }
        __syncthreads();
    }

    // ---- fused output compaction ----
    if (tid == 0) {
        int s = 0;
        for (int w = 0; w < NWORDS; ++w) { prefix[w] = s; s += __popcll(keepw[w]); }
    }
    float* o = out + (size_t)b * MAXDET * 6;
    for (int z = tid; z < MAXDET * 6; z += 1024) o[z] = 0.0f;
    __syncthreads();
    for (int i = tid; i < TOPK; i += 1024) {
        int w = i >> 6, bt = i & 63;
        if ((keepw[w] >> bt) & 1ULL) {
            int rank = prefix[w] + __popcll(keepw[w] & ((1ULL << bt) - 1ULL));
            if (rank < MAXDET) {
                int gi = b * TOPK + i;
                float* r = o + rank * 6;
                float4 bx = ((const float4*)g_box)[gi];
                r[0] = bx.x; r[1] = bx.y; r[2] = bx.z; r[3] = bx.w;
                r[4] = g_selScore[gi];
                r[5] = (float)g_selCls[gi];
            }
        }
    }
}

// ---------------- launch ---------------------------------------------------------------
extern "C" void kernel_launch(void* const* d_in, const int* in_sizes, int n_in,
                              void* d_out, int out_size) {
    const float* pred = (const float*)d_in[0];
    float* out = (float*)d_out;

    // 1) conf / argmax / order key : one warp per row
    {
        int rows = BATCH * NPRED;
        int threads = 256;
        int blocks = (rows * 32 + threads - 1) / threads;
        k_prep<<<blocks, threads>>>(pred);
    }
    // 2) exact top-4096 per batch + sort + fused gather
    k_select<<<BATCH, 1024>>>(pred);
    // 3) pairwise IoU mask (4 row-tiles per block)
    {
        dim3 g(NWORDS, NWORDS / 4, BATCH);
        k_mask<<<g, 256>>>();
    }
    // 4) greedy suppression + fused output
    k_suppress<<<BATCH, 1024>>>(out);
}